// round 13
// baseline (speedup 1.0000x reference)
#include <cuda_runtime.h>
#include <cuda_bf16.h>

typedef unsigned long long ull;

// ---------------- packed f32x2 helpers (FFMA2) ----------------
__device__ __forceinline__ ull f2pack(float lo, float hi) {
    ull d; asm("mov.b64 %0, {%1, %2};" : "=l"(d) : "f"(lo), "f"(hi)); return d;
}
__device__ __forceinline__ ull f2dup(float s) { return f2pack(s, s); }
__device__ __forceinline__ void f2unpack(float& lo, float& hi, ull s) {
    asm("mov.b64 {%0, %1}, %2;" : "=f"(lo), "=f"(hi) : "l"(s));
}
__device__ __forceinline__ ull f2fma(ull a, ull b, ull c) {
    ull d; asm("fma.rn.f32x2 %0, %1, %2, %3;" : "=l"(d) : "l"(a), "l"(b), "l"(c)); return d;
}

// ---------------- scratch (device globals; no allocation allowed) ----------------
__device__ float g_h1[4096 * 32 * 196];   // conv1 out (relu), NHWC [b][pos14x14][ci32]
__device__ float g_h2[4096 * 64 * 49];    // conv2 out (relu), row-major [m][co64]
__device__ int   g_idx[4096 * 49];        // VQ indices
__device__ float g_table[512 * 64];       // codebook @ dw0 + db0
__device__ float g_cbsq[512];             // ||codebook_c||^2 (XLA-order)
__device__ float g_vqpart[1568];          // per-block vq partial sums
__device__ float g_P[512 * 16 * 32];      // P[c][tap][co] = table[c] . dw1[tap][:][co]

// XLA GPU row-reduce order (matched reference in round 3).
__device__ __forceinline__ float xla_sumsq64(const float* v, int stride) {
    float p[64];
    #pragma unroll
    for (int k = 0; k < 64; k++) p[k] = __fmul_rn(v[k * stride], v[k * stride]);
    float a[32];
    #pragma unroll
    for (int i = 0; i < 32; i++) a[i] = __fadd_rn(p[i], p[i + 32]);
    #pragma unroll
    for (int s = 16; s > 0; s >>= 1)
        #pragma unroll
        for (int i = 0; i < 16; i++)
            if (i < s) a[i] = __fadd_rn(a[i], a[i + s]);
    return a[0];
}

// ---------------- K0: decode table + codebook norms ----------------
__global__ void k_prep(const float* __restrict__ cb, const float* __restrict__ dw0,
                       const float* __restrict__ db0) {
    int t = threadIdx.x;
    if (blockIdx.x < 128) {
        int id = blockIdx.x * 256 + t;
        int c = id >> 6, o = id & 63;
        float s = db0[o];
        const float* cr = cb + c * 64;
        #pragma unroll 8
        for (int i = 0; i < 64; i++) s += cr[i] * dw0[i * 64 + o];
        g_table[id] = s;
    } else {
        for (int c = t; c < 512; c += 256) g_cbsq[c] = xla_sumsq64(cb + c * 64, 1);
    }
}

// ---------------- K0b: P table (deconv1 folded through codebook) ----------------
__global__ void k_prep2(const float* __restrict__ dw1) {
    int id = blockIdx.x * 256 + threadIdx.x;   // 0..262143
    int co = id & 31, tap = (id >> 5) & 15, c = id >> 9;
    const float* tr = g_table + c * 64;
    const float* wr = dw1 + tap * 2048 + co;
    float s = 0.f;
    #pragma unroll 8
    for (int ci = 0; ci < 64; ci++) s += tr[ci] * wr[ci * 32];
    g_P[id] = s;
}

// ---------------- K1: conv1 4x4 s2 p1, 1->32, relu -> NHWC (FFMA2 co-pairs, 2 imgs/block) ----------------
__global__ void __launch_bounds__(416) k_conv1(const float* __restrict__ x,
                                               const float* __restrict__ w1,
                                               const float* __restrict__ b1) {
    __shared__ float xs[1800];                 // 2 x 30x30 zero-padded images
    __shared__ __align__(16) float ws[512];
    int b0 = blockIdx.x * 2, t = threadIdx.x;
    for (int l = t; l < 1800; l += 416) xs[l] = 0.f;
    for (int l = t; l < 512; l += 416) ws[l] = w1[l];
    __syncthreads();
    for (int l = t; l < 1568; l += 416) {
        int img = l / 784, pos = l % 784;
        int iy = pos / 28, ix = pos % 28;
        xs[img * 900 + (iy + 1) * 30 + ix + 1] = x[(b0 + img) * 784 + pos];
    }
    __syncthreads();
    if (t < 392) {
        int img = t / 196, p = t % 196;
        int oy = p / 14, ox = p % 14;
        const float* xsb = xs + img * 900;
        ull acc[16];
        const ulonglong2* b2p = (const ulonglong2*)b1;
        #pragma unroll
        for (int u = 0; u < 8; u++) {
            ulonglong2 bb = b2p[u];
            acc[2 * u] = bb.x; acc[2 * u + 1] = bb.y;
        }
        const ulonglong2* ws2 = (const ulonglong2*)ws;
        #pragma unroll
        for (int ky = 0; ky < 4; ky++)
        #pragma unroll
        for (int kx = 0; kx < 4; kx++) {
            float v = xsb[(2 * oy + ky) * 30 + 2 * ox + kx];
            ull vp = f2dup(v);
            int tb = (ky * 4 + kx) * 8;
            #pragma unroll
            for (int u = 0; u < 8; u++) {
                ulonglong2 wv = ws2[tb + u];
                acc[2 * u] = f2fma(vp, wv.x, acc[2 * u]);
                acc[2 * u + 1] = f2fma(vp, wv.y, acc[2 * u + 1]);
            }
        }
        float4* o = (float4*)(g_h1 + (b0 + img) * 6272 + p * 32);
        #pragma unroll
        for (int u = 0; u < 8; u++) {
            float a0, a1, a2, a3;
            f2unpack(a0, a1, acc[2 * u]);
            f2unpack(a2, a3, acc[2 * u + 1]);
            float4 v4;
            v4.x = fmaxf(a0, 0.f); v4.y = fmaxf(a1, 0.f);
            v4.z = fmaxf(a2, 0.f); v4.w = fmaxf(a3, 0.f);
            o[u] = v4;
        }
    }
}

// ---------------- K2: conv2 4x4 s2 p1, 32->64, relu (img-pair FFMA2, MLP-8 wload) ----------------
#define C2_CI_PAIR 546
#define C2_SMEM_WORDS (32 * C2_CI_PAIR)   // 17472 words = 69.9KB

__global__ void __launch_bounds__(112, 3) k_conv2(const float* __restrict__ w2,
                                                  const float* __restrict__ b2) {
    extern __shared__ __align__(16) float insm[];
    int t = threadIdx.x;
    int b0 = blockIdx.x * 2;
    for (int l = t; l < C2_SMEM_WORDS; l += 112) insm[l] = 0.f;
    __syncthreads();
    for (int l = t; l < 12544; l += 112) {
        int img = l & 1, ci = (l >> 1) & 31, pos = l >> 6;
        int iy = pos / 14, ix = pos % 14;
        insm[ci * C2_CI_PAIR + ((iy + 1) * 17 + ix + 1) * 2 + img] =
            g_h1[(b0 + img) * 6272 + pos * 32 + ci];
    }
    __syncthreads();
    int oy = t / 16, cog = t % 16, co0 = cog * 4;
    ull acc[7][4];
    {
        float4 bf = ((const float4*)b2)[cog];
        ull bd0 = f2dup(bf.x), bd1 = f2dup(bf.y), bd2 = f2dup(bf.z), bd3 = f2dup(bf.w);
        #pragma unroll
        for (int i = 0; i < 7; i++) {
            acc[i][0] = bd0; acc[i][1] = bd1; acc[i][2] = bd2; acc[i][3] = bd3;
        }
    }
    const float4* w24 = (const float4*)w2;
    const ull* insm2 = (const ull*)insm;
    for (int tap = 0; tap < 16; tap++) {
        int ky = tap >> 2, kx = tap & 3;
        int base = (2 * oy + ky) * 17 + kx;
        int wb = tap * 512 + cog;
        #pragma unroll
        for (int g = 0; g < 4; g++) {
            float4 wq[8];   // batched MLP-8 weight prefetch
            #pragma unroll
            for (int u = 0; u < 8; u++) wq[u] = __ldg(&w24[wb + (g * 8 + u) * 16]);
            #pragma unroll
            for (int u = 0; u < 8; u++) {
                int ci = g * 8 + u;
                ull wd0 = f2dup(wq[u].x), wd1 = f2dup(wq[u].y);
                ull wd2 = f2dup(wq[u].z), wd3 = f2dup(wq[u].w);
                const ull* ip = insm2 + ci * 273 + base;
                #pragma unroll
                for (int ox = 0; ox < 7; ox++) {
                    ull v = ip[2 * ox];
                    acc[ox][0] = f2fma(v, wd0, acc[ox][0]);
                    acc[ox][1] = f2fma(v, wd1, acc[ox][1]);
                    acc[ox][2] = f2fma(v, wd2, acc[ox][2]);
                    acc[ox][3] = f2fma(v, wd3, acc[ox][3]);
                }
            }
        }
    }
    size_t mA = (size_t)b0 * 49 + oy * 7;
    #pragma unroll
    for (int ox = 0; ox < 7; ox++) {
        float4 vA, vB;
        float lo, hi;
        f2unpack(lo, hi, acc[ox][0]); vA.x = fmaxf(lo, 0.f); vB.x = fmaxf(hi, 0.f);
        f2unpack(lo, hi, acc[ox][1]); vA.y = fmaxf(lo, 0.f); vB.y = fmaxf(hi, 0.f);
        f2unpack(lo, hi, acc[ox][2]); vA.z = fmaxf(lo, 0.f); vB.z = fmaxf(hi, 0.f);
        f2unpack(lo, hi, acc[ox][3]); vA.w = fmaxf(lo, 0.f); vB.w = fmaxf(hi, 0.f);
        *(float4*)(g_h2 + (mA + ox) * 64 + co0) = vA;
        *(float4*)(g_h2 + (mA + 49 + ox) * 64 + co0) = vB;
    }
}

// ---------------- K3: conv3 (1x1, 64->64) + VQ, fused (FFMA2, 3 blocks/SM) ----------------
// Phase-exclusive smem map (words), total 13376 = 53.5KB -> 3 blocks/SM:
//   [0,8320):      phase1 hs col-major [ci64][r128] stride130; phase2+ zsm [dim64][r128] stride130
//   [8320,12544):  phase1 wsm (4096); phase2 cb chunk float2[64 codes][33] swizzle; phase3 rs+ri
//   [12544,...):   cbsq64 | rowb128 | rowp128 | widx128 | sred256 | zsq128
#define HS_OFF    0
#define WSM_OFF   8320
#define CBF_OFF   8320
#define RS_OFF    8320
#define RI_OFF    10368
#define CBSQ_OFF  12544
#define ROWB_OFF  12608
#define ROWP_OFF  12736
#define WIDX_OFF  12864
#define SRED_OFF  12992
#define ZSQ_OFF   13248
#define K3_SMEM_WORDS 13376

__global__ void __launch_bounds__(256, 3) k_vq(const float* __restrict__ w3,
                                               const float* __restrict__ b3,
                                               const float* __restrict__ cb,
                                               float* __restrict__ out_z,
                                               float* __restrict__ out_zq,
                                               float* __restrict__ out_idx) {
    extern __shared__ __align__(16) float sm[];
    float* hs = sm + HS_OFF;            // phase1: col-major [ci][r], stride 130
    float* wsm = sm + WSM_OFF;
    float* zsm = sm + HS_OFF;           // phase2+: col-major [dim][r], stride 130 (overlays hs)
    float* rs = sm + RS_OFF;
    int* ri = (int*)(sm + RI_OFF);
    float* cbsqs = sm + CBSQ_OFF;
    int* rowb = (int*)(sm + ROWB_OFF);
    int* rowp = (int*)(sm + ROWP_OFF);
    int* widx = (int*)(sm + WIDX_OFF);
    float* sred = sm + SRED_OFF;
    float* zsq_s = sm + ZSQ_OFF;

    int t = threadIdx.x;
    int m0 = blockIdx.x * 128;
    if (t < 128) { int m = m0 + t; rowb[t] = m / 49; rowp[t] = m % 49; }
    for (int l = t; l < 4096; l += 256) wsm[l] = w3[l];
    for (int l = t; l < 8192; l += 256) {
        int r = l >> 6, ci = l & 63;
        hs[ci * 130 + r] = g_h2[(size_t)(m0 + r) * 64 + ci];
    }
    __syncthreads();
    // ---- GEMM1: z = h2 @ w3 + b3 (row-pair FFMA2; per-output chain ci 0..63 sequential).
    //      z kept in registers across the barrier, then written over hs (phase-exclusive).
    int rg = t >> 4, cg = t & 15;
    int r4 = rg * 4;                     // ull pair base (rows r0..r0+7)
    ull zacc[4][4];                      // [pair][co]
    {
        float4 b4 = ((const float4*)b3)[cg];
        ull bd0 = f2dup(b4.x), bd1 = f2dup(b4.y), bd2 = f2dup(b4.z), bd3 = f2dup(b4.w);
        #pragma unroll
        for (int p = 0; p < 4; p++) {
            zacc[p][0] = bd0; zacc[p][1] = bd1; zacc[p][2] = bd2; zacc[p][3] = bd3;
        }
        const ull* hsu = (const ull*)hs;
        const float4* wsm4 = (const float4*)wsm;
        #pragma unroll 4
        for (int ci = 0; ci < 64; ci++) {
            float4 w4 = wsm4[ci * 16 + cg];
            ull wd0 = f2dup(w4.x), wd1 = f2dup(w4.y), wd2 = f2dup(w4.z), wd3 = f2dup(w4.w);
            ull hp[4];
            #pragma unroll
            for (int p = 0; p < 4; p++) hp[p] = hsu[ci * 65 + r4 + p];
            #pragma unroll
            for (int p = 0; p < 4; p++) {
                zacc[p][0] = f2fma(hp[p], wd0, zacc[p][0]);
                zacc[p][1] = f2fma(hp[p], wd1, zacc[p][1]);
                zacc[p][2] = f2fma(hp[p], wd2, zacc[p][2]);
                zacc[p][3] = f2fma(hp[p], wd3, zacc[p][3]);
            }
        }
    }
    __syncthreads();   // all hs reads done; region becomes zsm
    {
        ull* zsu = (ull*)zsm;
        int co0 = cg * 4;
        #pragma unroll
        for (int j = 0; j < 4; j++)
            #pragma unroll
            for (int p = 0; p < 4; p++)
                zsu[(co0 + j) * 65 + r4 + p] = zacc[p][j];
    }
    __syncthreads();
    // zsq per row (XLA order); coalesced NCHW z write
    if (t < 128) zsq_s[t] = xla_sumsq64(zsm + t, 130);
    for (int l = t; l < 8192; l += 256) {
        int r = l & 127, co = l >> 7;
        out_z[rowb[r] * 3136 + co * 49 + rowp[r]] = zsm[co * 130 + r];
    }
    // ---- distance argmin: 8 chunks of 64 codes; thread handles codes c = cg + 16*jc
    float bsv[8]; int bix[8];
    #pragma unroll
    for (int j = 0; j < 8; j++) { bsv[j] = 3.4e38f; bix[j] = 0; }
    int r0 = rg * 8;
    float2* cbf = (float2*)(sm + CBF_OFF);   // [c][k] slot = c*33 + k (k = dim/2)
    const ull* zsu = (const ull*)zsm;
    for (int cc = 0; cc < 8; cc++) {
        __syncthreads();
        {
            const float2* cbg = (const float2*)(cb) + cc * 2048;   // 64 codes x 32 float2
            for (int l = t; l < 2048; l += 256) {
                int c = l >> 5, k = l & 31;
                cbf[c * 33 + k] = cbg[l];
            }
        }
        if (t < 64) cbsqs[t] = g_cbsq[cc * 64 + t];
        __syncthreads();
        ull acc[4][4];   // [pair][jc]
        #pragma unroll
        for (int p = 0; p < 4; p++)
            #pragma unroll
            for (int jc = 0; jc < 4; jc++) acc[p][jc] = 0ull;
        for (int d4 = 0; d4 < 16; d4++) {
            ull zp0[4], zp1[4];
            // half A: dims 4d4, 4d4+1  (k = 2*d4)
            #pragma unroll
            for (int p = 0; p < 4; p++) zp0[p] = zsu[(4 * d4 + 0) * 65 + r4 + p];
            #pragma unroll
            for (int p = 0; p < 4; p++) zp1[p] = zsu[(4 * d4 + 1) * 65 + r4 + p];
            #pragma unroll
            for (int jc = 0; jc < 4; jc++) {
                int c = cg + 16 * jc;
                float2 cv = cbf[c * 33 + 2 * d4];
                ull cd0 = f2dup(cv.x), cd1 = f2dup(cv.y);
                #pragma unroll
                for (int p = 0; p < 4; p++) {
                    ull a = acc[p][jc];
                    a = f2fma(zp0[p], cd0, a);
                    a = f2fma(zp1[p], cd1, a);
                    acc[p][jc] = a;
                }
            }
            // half B: dims 4d4+2, 4d4+3  (k = 2*d4+1)
            #pragma unroll
            for (int p = 0; p < 4; p++) zp0[p] = zsu[(4 * d4 + 2) * 65 + r4 + p];
            #pragma unroll
            for (int p = 0; p < 4; p++) zp1[p] = zsu[(4 * d4 + 3) * 65 + r4 + p];
            #pragma unroll
            for (int jc = 0; jc < 4; jc++) {
                int c = cg + 16 * jc;
                float2 cv = cbf[c * 33 + 2 * d4 + 1];
                ull cd2 = f2dup(cv.x), cd3 = f2dup(cv.y);
                #pragma unroll
                for (int p = 0; p < 4; p++) {
                    ull a = acc[p][jc];
                    a = f2fma(zp0[p], cd2, a);
                    a = f2fma(zp1[p], cd3, a);
                    acc[p][jc] = a;
                }
            }
        }
        #pragma unroll
        for (int jc = 0; jc < 4; jc++) {
            int c = cg + 16 * jc;
            float qn = cbsqs[c];
            int id = cc * 64 + c;
            #pragma unroll
            for (int p = 0; p < 4; p++) {
                float d0, d1;
                f2unpack(d0, d1, acc[p][jc]);
                {
                    float T = __fadd_rn(zsq_s[r0 + 2 * p], qn);
                    float d = __fadd_rn(T, -__fmul_rn(2.0f, d0));
                    if (d < bsv[2 * p]) { bsv[2 * p] = d; bix[2 * p] = id; }
                }
                {
                    float T = __fadd_rn(zsq_s[r0 + 2 * p + 1], qn);
                    float d = __fadd_rn(T, -__fmul_rn(2.0f, d1));
                    if (d < bsv[2 * p + 1]) { bsv[2 * p + 1] = d; bix[2 * p + 1] = id; }
                }
            }
        }
    }
    __syncthreads();   // cb region dead; rs/ri overlay
    #pragma unroll
    for (int j = 0; j < 8; j++) { rs[(r0 + j) * 16 + cg] = bsv[j]; ri[(r0 + j) * 16 + cg] = bix[j]; }
    __syncthreads();
    if (t < 128) {
        float best = rs[t * 16]; int bid = ri[t * 16];
        #pragma unroll
        for (int k = 1; k < 16; k++) {
            float s = rs[t * 16 + k]; int id = ri[t * 16 + k];
            if (s < best || (s == best && id < bid)) { best = s; bid = id; }
        }
        widx[t] = bid;
        int m = m0 + t;
        g_idx[m] = bid;
        out_idx[m] = (float)bid;
    }
    __syncthreads();
    float psum = 0.f;
    for (int l = t; l < 8192; l += 256) {
        int r = l & 127, co = l >> 7;
        float q = cb[widx[r] * 64 + co];
        float zv = zsm[co * 130 + r];
        float st = __fadd_rn(zv, __fadd_rn(q, -zv));
        out_zq[rowb[r] * 3136 + co * 49 + rowp[r]] = st;
        float d = zv - q;
        psum += d * d;
    }
    sred[t] = psum;
    __syncthreads();
    for (int s = 128; s > 0; s >>= 1) {
        if (t < s) sred[t] += sred[t + s];
        __syncthreads();
    }
    if (t == 0) g_vqpart[blockIdx.x] = sred[0];
}

// ---------------- K3b: vq loss final reduce ----------------
__global__ void k_vqred(float* __restrict__ out_vq) {
    __shared__ float sred[256];
    int t = threadIdx.x;
    float s = 0.f;
    for (int l = t; l < 1568; l += 256) s += g_vqpart[l];
    sred[t] = s;
    __syncthreads();
    for (int k = 128; k > 0; k >>= 1) { if (t < k) sred[t] += sred[t + k]; __syncthreads(); }
    if (t == 0) out_vq[0] = sred[0] * 1.25f / (200704.f * 64.f);
}

// ---------------- K4: fused deconv1(P-table) + relu + deconv2 + sigmoid ----------------
__global__ void __launch_bounds__(256) k_dec(const float* __restrict__ db1,
                                             const float* __restrict__ dw2,
                                             const float* __restrict__ db2,
                                             float* __restrict__ out_recon) {
    __shared__ float d1s[32 * 273];   // [ci][16x17 padded, stride 273]
    __shared__ float ws[512];
    __shared__ int sidx[49];
    int t = threadIdx.x, b = blockIdx.x;
    if (t < 49) sidx[t] = g_idx[b * 49 + t];
    for (int l = t; l < 512; l += 256) ws[l] = dw2[l];
    for (int l = t; l < 32 * 273; l += 256) d1s[l] = 0.f;
    __syncthreads();
    const float4* P4 = (const float4*)g_P;
    const float4* db14 = (const float4*)db1;
    for (int l = t; l < 1568; l += 256) {
        int g = l / 196, pos = l % 196;
        int oy = pos / 14, ox = pos % 14;
        float4 a = __ldg(&db14[g]);
        int kyb = oy & 1, kxb = ox & 1;
        #pragma unroll
        for (int dy = 0; dy < 2; dy++) {
            int ky = kyb + 2 * dy;
            int i = (oy + ky - 2) >> 1;
            if ((unsigned)i < 7u) {
                #pragma unroll
                for (int dx = 0; dx < 2; dx++) {
                    int kx = kxb + 2 * dx;
                    int j = (ox + kx - 2) >> 1;
                    if ((unsigned)j < 7u) {
                        int c = sidx[i * 7 + j];
                        float4 p = __ldg(&P4[(c * 16 + ky * 4 + kx) * 8 + g]);
                        a.x += p.x; a.y += p.y; a.z += p.z; a.w += p.w;
                    }
                }
            }
        }
        int sp = (oy + 1) * 17 + ox + 1;
        d1s[(4 * g + 0) * 273 + sp] = fmaxf(a.x, 0.f);
        d1s[(4 * g + 1) * 273 + sp] = fmaxf(a.y, 0.f);
        d1s[(4 * g + 2) * 273 + sp] = fmaxf(a.z, 0.f);
        d1s[(4 * g + 3) * 273 + sp] = fmaxf(a.w, 0.f);
    }
    __syncthreads();
    if (t < 112) {
        int par = t / 28, rem2 = t % 28;
        int q = rem2 >> 1, rh = rem2 & 1, r0c = rh * 7;
        int ay = par >> 1, ax = par & 1;
        float acc[7];
        float bv = db2[0];
        #pragma unroll
        for (int r = 0; r < 7; r++) acc[r] = bv;
        #pragma unroll
        for (int dy = 0; dy < 2; dy++)
        #pragma unroll
        for (int dx = 0; dx < 2; dx++) {
            int ky = 2 * dy + ay, kx = 2 * dx + ax;
            const float* inr = d1s + (q + dy + ay) * 17 + r0c + dx + ax;
            const float* wp = ws + (ky * 4 + kx) * 32;
            #pragma unroll 8
            for (int ci = 0; ci < 32; ci++) {
                float w = wp[ci];
                const float* ip = inr + ci * 273;
                #pragma unroll
                for (int r = 0; r < 7; r++) acc[r] += ip[r] * w;
            }
        }
        int oy = 2 * q + ay;
        float* ob = out_recon + b * 784 + oy * 28 + ax;
        #pragma unroll
        for (int r = 0; r < 7; r++) {
            float v = acc[r];
            ob[2 * (r0c + r)] = 1.f / (1.f + __expf(-v));
        }
    }
}

// ---------------- launch ----------------
extern "C" void kernel_launch(void* const* d_in, const int* in_sizes, int n_in,
                              void* d_out, int out_size) {
    const float* x   = (const float*)d_in[0];
    const float* w1  = (const float*)d_in[1];
    const float* b1  = (const float*)d_in[2];
    const float* w2  = (const float*)d_in[3];
    const float* b2  = (const float*)d_in[4];
    const float* w3  = (const float*)d_in[5];
    const float* b3  = (const float*)d_in[6];
    const float* cb  = (const float*)d_in[7];
    const float* dw0 = (const float*)d_in[8];
    const float* db0 = (const float*)d_in[9];
    const float* dw1 = (const float*)d_in[10];
    const float* db1 = (const float*)d_in[11];
    const float* dw2 = (const float*)d_in[12];
    const float* db2 = (const float*)d_in[13];

    float* out = (float*)d_out;
    float* out_recon = out;                       // 3,211,264
    float* out_z     = out_recon + 3211264;       // 12,845,056
    float* out_zq    = out_z + 12845056;          // 12,845,056
    float* out_vq    = out_zq + 12845056;         // 1
    float* out_idx   = out_vq + 1;                // 200,704

    cudaFuncSetAttribute(k_conv2, cudaFuncAttributeMaxDynamicSharedMemorySize, C2_SMEM_WORDS * 4);
    cudaFuncSetAttribute(k_vq,    cudaFuncAttributeMaxDynamicSharedMemorySize, K3_SMEM_WORDS * 4);

    k_prep<<<129, 256>>>(cb, dw0, db0);
    k_prep2<<<1024, 256>>>(dw1);
    k_conv1<<<2048, 416>>>(x, w1, b1);
    k_conv2<<<2048, 112, C2_SMEM_WORDS * 4>>>(w2, b2);
    k_vq<<<1568, 256, K3_SMEM_WORDS * 4>>>(w3, b3, cb, out_z, out_zq, out_idx);
    k_vqred<<<1, 256>>>(out_vq);
    k_dec<<<4096, 256>>>(db1, dw2, db2, out_recon);
}

// round 14
// speedup vs baseline: 1.6587x; 1.6587x over previous
#include <cuda_runtime.h>
#include <cuda_bf16.h>

typedef unsigned long long ull;

// ---------------- packed f32x2 helpers (FFMA2) ----------------
__device__ __forceinline__ ull f2pack(float lo, float hi) {
    ull d; asm("mov.b64 %0, {%1, %2};" : "=l"(d) : "f"(lo), "f"(hi)); return d;
}
__device__ __forceinline__ ull f2dup(float s) { return f2pack(s, s); }
__device__ __forceinline__ void f2unpack(float& lo, float& hi, ull s) {
    asm("mov.b64 {%0, %1}, %2;" : "=f"(lo), "=f"(hi) : "l"(s));
}
__device__ __forceinline__ ull f2fma(ull a, ull b, ull c) {
    ull d; asm("fma.rn.f32x2 %0, %1, %2, %3;" : "=l"(d) : "l"(a), "l"(b), "l"(c)); return d;
}

// ---------------- scratch (device globals; no allocation allowed) ----------------
__device__ float g_h1[4096 * 32 * 196];   // conv1 out (relu), NHWC [b][pos14x14][ci32]
__device__ float g_h2[4096 * 64 * 49];    // conv2 out (relu), row-major [m][co64]
__device__ int   g_idx[4096 * 49];        // VQ indices
__device__ float g_table[512 * 64];       // codebook @ dw0 + db0
__device__ float g_cbsq[512];             // ||codebook_c||^2 (XLA-order)
__device__ float g_vqpart[1568];          // per-block vq partial sums
__device__ float g_P[512 * 16 * 32];      // P[c][tap][co] = table[c] . dw1[tap][:][co]

// XLA GPU row-reduce order (matched reference in round 3).
__device__ __forceinline__ float xla_sumsq64(const float* v, int stride) {
    float p[64];
    #pragma unroll
    for (int k = 0; k < 64; k++) p[k] = __fmul_rn(v[k * stride], v[k * stride]);
    float a[32];
    #pragma unroll
    for (int i = 0; i < 32; i++) a[i] = __fadd_rn(p[i], p[i + 32]);
    #pragma unroll
    for (int s = 16; s > 0; s >>= 1)
        #pragma unroll
        for (int i = 0; i < 16; i++)
            if (i < s) a[i] = __fadd_rn(a[i], a[i + s]);
    return a[0];
}

// ---------------- K0: decode table + codebook norms ----------------
__global__ void k_prep(const float* __restrict__ cb, const float* __restrict__ dw0,
                       const float* __restrict__ db0) {
    int t = threadIdx.x;
    if (blockIdx.x < 128) {
        int id = blockIdx.x * 256 + t;
        int c = id >> 6, o = id & 63;
        float s = db0[o];
        const float* cr = cb + c * 64;
        #pragma unroll 8
        for (int i = 0; i < 64; i++) s += cr[i] * dw0[i * 64 + o];
        g_table[id] = s;
    } else {
        for (int c = t; c < 512; c += 256) g_cbsq[c] = xla_sumsq64(cb + c * 64, 1);
    }
}

// ---------------- K0b: P table (deconv1 folded through codebook) ----------------
__global__ void k_prep2(const float* __restrict__ dw1) {
    int id = blockIdx.x * 256 + threadIdx.x;   // 0..262143
    int co = id & 31, tap = (id >> 5) & 15, c = id >> 9;
    const float* tr = g_table + c * 64;
    const float* wr = dw1 + tap * 2048 + co;
    float s = 0.f;
    #pragma unroll 8
    for (int ci = 0; ci < 64; ci++) s += tr[ci] * wr[ci * 32];
    g_P[id] = s;
}

// ---------------- K1: conv1 4x4 s2 p1, 1->32, relu -> NHWC (FFMA2 co-pairs) ----------------
__global__ void __launch_bounds__(256) k_conv1(const float* __restrict__ x,
                                               const float* __restrict__ w1,
                                               const float* __restrict__ b1) {
    __shared__ float xs[900];
    __shared__ __align__(16) float ws[512];
    int b = blockIdx.x, t = threadIdx.x;
    for (int l = t; l < 900; l += 256) xs[l] = 0.f;
    for (int l = t; l < 512; l += 256) ws[l] = w1[l];
    __syncthreads();
    for (int l = t; l < 784; l += 256) {
        int iy = l / 28, ix = l % 28;
        xs[(iy + 1) * 30 + ix + 1] = x[b * 784 + l];
    }
    __syncthreads();
    if (t < 196) {
        int oy = t / 14, ox = t % 14;
        ull acc[16];
        const ulonglong2* b2p = (const ulonglong2*)b1;
        #pragma unroll
        for (int u = 0; u < 8; u++) {
            ulonglong2 bb = b2p[u];
            acc[2 * u] = bb.x; acc[2 * u + 1] = bb.y;
        }
        const ulonglong2* ws2 = (const ulonglong2*)ws;
        #pragma unroll
        for (int ky = 0; ky < 4; ky++)
        #pragma unroll
        for (int kx = 0; kx < 4; kx++) {
            float v = xs[(2 * oy + ky) * 30 + 2 * ox + kx];
            ull vp = f2dup(v);
            int tb = (ky * 4 + kx) * 8;
            #pragma unroll
            for (int u = 0; u < 8; u++) {
                ulonglong2 wv = ws2[tb + u];
                acc[2 * u] = f2fma(vp, wv.x, acc[2 * u]);
                acc[2 * u + 1] = f2fma(vp, wv.y, acc[2 * u + 1]);
            }
        }
        float4* o = (float4*)(g_h1 + b * 6272 + t * 32);
        #pragma unroll
        for (int u = 0; u < 8; u++) {
            float a0, a1, a2, a3;
            f2unpack(a0, a1, acc[2 * u]);
            f2unpack(a2, a3, acc[2 * u + 1]);
            float4 v4;
            v4.x = fmaxf(a0, 0.f); v4.y = fmaxf(a1, 0.f);
            v4.z = fmaxf(a2, 0.f); v4.w = fmaxf(a3, 0.f);
            o[u] = v4;
        }
    }
}

// ---------------- K2: conv2 4x4 s2 p1, 32->64, relu (img-pair FFMA2, 224 thr / 2-co) ----------------
#define C2_CI_PAIR 546
#define C2_SMEM_WORDS (32 * C2_CI_PAIR)   // 17472 words = 69.9KB

__global__ void __launch_bounds__(224, 3) k_conv2(const float* __restrict__ w2,
                                                  const float* __restrict__ b2) {
    extern __shared__ __align__(16) float insm[];
    int t = threadIdx.x;
    int b0 = blockIdx.x * 2;
    for (int l = t; l < C2_SMEM_WORDS; l += 224) insm[l] = 0.f;
    __syncthreads();
    for (int l = t; l < 12544; l += 224) {
        int img = l & 1, ci = (l >> 1) & 31, pos = l >> 6;
        int iy = pos / 14, ix = pos % 14;
        insm[ci * C2_CI_PAIR + ((iy + 1) * 17 + ix + 1) * 2 + img] =
            g_h1[(b0 + img) * 6272 + pos * 32 + ci];
    }
    __syncthreads();
    int oy = t >> 5, cog = t & 31, co0 = cog * 2;   // warp = one oy; thread owns 2 co
    ull acc[7][2];
    {
        float2 bf = ((const float2*)b2)[cog];
        ull bd0 = f2dup(bf.x), bd1 = f2dup(bf.y);
        #pragma unroll
        for (int i = 0; i < 7; i++) { acc[i][0] = bd0; acc[i][1] = bd1; }
    }
    const float2* w22 = (const float2*)w2;          // index = tap*1024 + ci*32 + cog
    const ull* insm2 = (const ull*)insm;
    for (int tap = 0; tap < 16; tap++) {
        int ky = tap >> 2, kx = tap & 3;
        int base = (2 * oy + ky) * 17 + kx;
        int wb = tap * 1024 + cog;
        #pragma unroll
        for (int g = 0; g < 4; g++) {
            float2 wq[8];   // batched MLP-8 weight prefetch
            #pragma unroll
            for (int u = 0; u < 8; u++) wq[u] = __ldg(&w22[wb + (g * 8 + u) * 32]);
            #pragma unroll
            for (int u = 0; u < 8; u++) {
                int ci = g * 8 + u;
                ull wd0 = f2dup(wq[u].x), wd1 = f2dup(wq[u].y);
                const ull* ip = insm2 + ci * 273 + base;
                #pragma unroll
                for (int ox = 0; ox < 7; ox++) {
                    ull v = ip[2 * ox];
                    acc[ox][0] = f2fma(v, wd0, acc[ox][0]);
                    acc[ox][1] = f2fma(v, wd1, acc[ox][1]);
                }
            }
        }
    }
    size_t mA = (size_t)b0 * 49 + oy * 7;
    #pragma unroll
    for (int ox = 0; ox < 7; ox++) {
        float a0, a1, b0f, b1f;
        f2unpack(a0, b0f, acc[ox][0]);   // lo=imgA, hi=imgB (co0)
        f2unpack(a1, b1f, acc[ox][1]);   // (co0+1)
        float2 vA, vB;
        vA.x = fmaxf(a0, 0.f); vA.y = fmaxf(a1, 0.f);
        vB.x = fmaxf(b0f, 0.f); vB.y = fmaxf(b1f, 0.f);
        *(float2*)(g_h2 + (mA + ox) * 64 + co0) = vA;
        *(float2*)(g_h2 + (mA + 49 + ox) * 64 + co0) = vB;
    }
}

// ---------------- K3: conv3 (1x1, 64->64) + VQ, fused (FFMA2, 3 blocks/SM) ----------------
// Phase-exclusive smem map (words), total 13376 = 53.5KB -> 3 blocks/SM:
//   [0,8320):      phase1 hs col-major [ci64][r128] stride130; phase2+ zsm [dim64][r128] stride130
//   [8320,12544):  phase1 wsm (4096); phase2 cb chunk float2[64 codes][33]; phase3 rs+ri
//   [12544,...):   cbsq64 | rowb128 | rowp128 | widx128 | sred256 | zsq128
#define HS_OFF    0
#define WSM_OFF   8320
#define CBF_OFF   8320
#define RS_OFF    8320
#define RI_OFF    10368
#define CBSQ_OFF  12544
#define ROWB_OFF  12608
#define ROWP_OFF  12736
#define WIDX_OFF  12864
#define SRED_OFF  12992
#define ZSQ_OFF   13248
#define K3_SMEM_WORDS 13376

__global__ void __launch_bounds__(256, 3) k_vq(const float* __restrict__ w3,
                                               const float* __restrict__ b3,
                                               const float* __restrict__ cb,
                                               float* __restrict__ out_z,
                                               float* __restrict__ out_zq,
                                               float* __restrict__ out_idx) {
    extern __shared__ __align__(16) float sm[];
    float* hs = sm + HS_OFF;            // phase1: col-major [ci][r], stride 130
    float* wsm = sm + WSM_OFF;
    float* zsm = sm + HS_OFF;           // phase2+: col-major [dim][r], stride 130 (overlays hs)
    float* rs = sm + RS_OFF;
    int* ri = (int*)(sm + RI_OFF);
    float* cbsqs = sm + CBSQ_OFF;
    int* rowb = (int*)(sm + ROWB_OFF);
    int* rowp = (int*)(sm + ROWP_OFF);
    int* widx = (int*)(sm + WIDX_OFF);
    float* sred = sm + SRED_OFF;
    float* zsq_s = sm + ZSQ_OFF;

    int t = threadIdx.x;
    int m0 = blockIdx.x * 128;
    if (t < 128) { int m = m0 + t; rowb[t] = m / 49; rowp[t] = m % 49; }
    for (int l = t; l < 4096; l += 256) wsm[l] = w3[l];
    for (int l = t; l < 8192; l += 256) {
        int r = l >> 6, ci = l & 63;
        hs[ci * 130 + r] = g_h2[(size_t)(m0 + r) * 64 + ci];
    }
    __syncthreads();
    // ---- GEMM1: z = h2 @ w3 + b3 (row-pair FFMA2; per-output chain ci 0..63 sequential).
    int rg = t >> 4, cg = t & 15;
    int r4 = rg * 4;                     // ull pair base (rows r0..r0+7)
    ull zacc[4][4];                      // [pair][co]
    {
        float4 b4 = ((const float4*)b3)[cg];
        ull bd0 = f2dup(b4.x), bd1 = f2dup(b4.y), bd2 = f2dup(b4.z), bd3 = f2dup(b4.w);
        #pragma unroll
        for (int p = 0; p < 4; p++) {
            zacc[p][0] = bd0; zacc[p][1] = bd1; zacc[p][2] = bd2; zacc[p][3] = bd3;
        }
        const ull* hsu = (const ull*)hs;
        const float4* wsm4 = (const float4*)wsm;
        #pragma unroll 4
        for (int ci = 0; ci < 64; ci++) {
            float4 w4 = wsm4[ci * 16 + cg];
            ull wd0 = f2dup(w4.x), wd1 = f2dup(w4.y), wd2 = f2dup(w4.z), wd3 = f2dup(w4.w);
            ull hp[4];
            #pragma unroll
            for (int p = 0; p < 4; p++) hp[p] = hsu[ci * 65 + r4 + p];
            #pragma unroll
            for (int p = 0; p < 4; p++) {
                zacc[p][0] = f2fma(hp[p], wd0, zacc[p][0]);
                zacc[p][1] = f2fma(hp[p], wd1, zacc[p][1]);
                zacc[p][2] = f2fma(hp[p], wd2, zacc[p][2]);
                zacc[p][3] = f2fma(hp[p], wd3, zacc[p][3]);
            }
        }
    }
    __syncthreads();   // all hs reads done; region becomes zsm
    {
        ull* zsu = (ull*)zsm;
        int co0 = cg * 4;
        #pragma unroll
        for (int j = 0; j < 4; j++)
            #pragma unroll
            for (int p = 0; p < 4; p++)
                zsu[(co0 + j) * 65 + r4 + p] = zacc[p][j];
    }
    __syncthreads();
    // zsq per row (XLA order); coalesced NCHW z write
    if (t < 128) zsq_s[t] = xla_sumsq64(zsm + t, 130);
    for (int l = t; l < 8192; l += 256) {
        int r = l & 127, co = l >> 7;
        out_z[rowb[r] * 3136 + co * 49 + rowp[r]] = zsm[co * 130 + r];
    }
    // ---- distance argmin: 8 chunks of 64 codes; thread handles codes c = cg + 16*jc
    float bsv[8]; int bix[8];
    #pragma unroll
    for (int j = 0; j < 8; j++) { bsv[j] = 3.4e38f; bix[j] = 0; }
    int r0 = rg * 8;
    float2* cbf = (float2*)(sm + CBF_OFF);   // [c][k] slot = c*33 + k (k = dim/2)
    const ull* zsu = (const ull*)zsm;
    for (int cc = 0; cc < 8; cc++) {
        __syncthreads();
        {
            const float2* cbg = (const float2*)(cb) + cc * 2048;   // 64 codes x 32 float2
            for (int l = t; l < 2048; l += 256) {
                int c = l >> 5, k = l & 31;
                cbf[c * 33 + k] = cbg[l];
            }
        }
        if (t < 64) cbsqs[t] = g_cbsq[cc * 64 + t];
        __syncthreads();
        ull acc[4][4];   // [pair][jc]
        #pragma unroll
        for (int p = 0; p < 4; p++)
            #pragma unroll
            for (int jc = 0; jc < 4; jc++) acc[p][jc] = 0ull;
        for (int d4 = 0; d4 < 16; d4++) {
            ull zp0[4], zp1[4];
            // half A: dims 4d4, 4d4+1  (k = 2*d4)
            #pragma unroll
            for (int p = 0; p < 4; p++) zp0[p] = zsu[(4 * d4 + 0) * 65 + r4 + p];
            #pragma unroll
            for (int p = 0; p < 4; p++) zp1[p] = zsu[(4 * d4 + 1) * 65 + r4 + p];
            #pragma unroll
            for (int jc = 0; jc < 4; jc++) {
                int c = cg + 16 * jc;
                float2 cv = cbf[c * 33 + 2 * d4];
                ull cd0 = f2dup(cv.x), cd1 = f2dup(cv.y);
                #pragma unroll
                for (int p = 0; p < 4; p++) {
                    ull a = acc[p][jc];
                    a = f2fma(zp0[p], cd0, a);
                    a = f2fma(zp1[p], cd1, a);
                    acc[p][jc] = a;
                }
            }
            // half B: dims 4d4+2, 4d4+3  (k = 2*d4+1)
            #pragma unroll
            for (int p = 0; p < 4; p++) zp0[p] = zsu[(4 * d4 + 2) * 65 + r4 + p];
            #pragma unroll
            for (int p = 0; p < 4; p++) zp1[p] = zsu[(4 * d4 + 3) * 65 + r4 + p];
            #pragma unroll
            for (int jc = 0; jc < 4; jc++) {
                int c = cg + 16 * jc;
                float2 cv = cbf[c * 33 + 2 * d4 + 1];
                ull cd2 = f2dup(cv.x), cd3 = f2dup(cv.y);
                #pragma unroll
                for (int p = 0; p < 4; p++) {
                    ull a = acc[p][jc];
                    a = f2fma(zp0[p], cd2, a);
                    a = f2fma(zp1[p], cd3, a);
                    acc[p][jc] = a;
                }
            }
        }
        #pragma unroll
        for (int jc = 0; jc < 4; jc++) {
            int c = cg + 16 * jc;
            float qn = cbsqs[c];
            int id = cc * 64 + c;
            #pragma unroll
            for (int p = 0; p < 4; p++) {
                float d0, d1;
                f2unpack(d0, d1, acc[p][jc]);
                {
                    float T = __fadd_rn(zsq_s[r0 + 2 * p], qn);
                    float d = __fadd_rn(T, -__fmul_rn(2.0f, d0));
                    if (d < bsv[2 * p]) { bsv[2 * p] = d; bix[2 * p] = id; }
                }
                {
                    float T = __fadd_rn(zsq_s[r0 + 2 * p + 1], qn);
                    float d = __fadd_rn(T, -__fmul_rn(2.0f, d1));
                    if (d < bsv[2 * p + 1]) { bsv[2 * p + 1] = d; bix[2 * p + 1] = id; }
                }
            }
        }
    }
    __syncthreads();   // cb region dead; rs/ri overlay
    #pragma unroll
    for (int j = 0; j < 8; j++) { rs[(r0 + j) * 16 + cg] = bsv[j]; ri[(r0 + j) * 16 + cg] = bix[j]; }
    __syncthreads();
    if (t < 128) {
        float best = rs[t * 16]; int bid = ri[t * 16];
        #pragma unroll
        for (int k = 1; k < 16; k++) {
            float s = rs[t * 16 + k]; int id = ri[t * 16 + k];
            if (s < best || (s == best && id < bid)) { best = s; bid = id; }
        }
        widx[t] = bid;
        int m = m0 + t;
        g_idx[m] = bid;
        out_idx[m] = (float)bid;
    }
    __syncthreads();
    float psum = 0.f;
    for (int l = t; l < 8192; l += 256) {
        int r = l & 127, co = l >> 7;
        float q = cb[widx[r] * 64 + co];
        float zv = zsm[co * 130 + r];
        float st = __fadd_rn(zv, __fadd_rn(q, -zv));
        out_zq[rowb[r] * 3136 + co * 49 + rowp[r]] = st;
        float d = zv - q;
        psum += d * d;
    }
    sred[t] = psum;
    __syncthreads();
    for (int s = 128; s > 0; s >>= 1) {
        if (t < s) sred[t] += sred[t + s];
        __syncthreads();
    }
    if (t == 0) g_vqpart[blockIdx.x] = sred[0];
}

// ---------------- K3b: vq loss final reduce ----------------
__global__ void k_vqred(float* __restrict__ out_vq) {
    __shared__ float sred[256];
    int t = threadIdx.x;
    float s = 0.f;
    for (int l = t; l < 1568; l += 256) s += g_vqpart[l];
    sred[t] = s;
    __syncthreads();
    for (int k = 128; k > 0; k >>= 1) { if (t < k) sred[t] += sred[t + k]; __syncthreads(); }
    if (t == 0) out_vq[0] = sred[0] * 1.25f / (200704.f * 64.f);
}

// ---------------- K4: fused deconv1(P-table) + relu + deconv2 + sigmoid ----------------
__global__ void __launch_bounds__(256) k_dec(const float* __restrict__ db1,
                                             const float* __restrict__ dw2,
                                             const float* __restrict__ db2,
                                             float* __restrict__ out_recon) {
    __shared__ float d1s[32 * 273];   // [ci][16x17 padded, stride 273]
    __shared__ float ws[512];
    __shared__ int sidx[49];
    int t = threadIdx.x, b = blockIdx.x;
    if (t < 49) sidx[t] = g_idx[b * 49 + t];
    for (int l = t; l < 512; l += 256) ws[l] = dw2[l];
    for (int l = t; l < 32 * 273; l += 256) d1s[l] = 0.f;
    __syncthreads();
    const float4* P4 = (const float4*)g_P;
    const float4* db14 = (const float4*)db1;
    for (int l = t; l < 1568; l += 256) {
        int g = l / 196, pos = l % 196;
        int oy = pos / 14, ox = pos % 14;
        float4 a = __ldg(&db14[g]);
        int kyb = oy & 1, kxb = ox & 1;
        #pragma unroll
        for (int dy = 0; dy < 2; dy++) {
            int ky = kyb + 2 * dy;
            int i = (oy + ky - 2) >> 1;
            if ((unsigned)i < 7u) {
                #pragma unroll
                for (int dx = 0; dx < 2; dx++) {
                    int kx = kxb + 2 * dx;
                    int j = (ox + kx - 2) >> 1;
                    if ((unsigned)j < 7u) {
                        int c = sidx[i * 7 + j];
                        float4 p = __ldg(&P4[(c * 16 + ky * 4 + kx) * 8 + g]);
                        a.x += p.x; a.y += p.y; a.z += p.z; a.w += p.w;
                    }
                }
            }
        }
        int sp = (oy + 1) * 17 + ox + 1;
        d1s[(4 * g + 0) * 273 + sp] = fmaxf(a.x, 0.f);
        d1s[(4 * g + 1) * 273 + sp] = fmaxf(a.y, 0.f);
        d1s[(4 * g + 2) * 273 + sp] = fmaxf(a.z, 0.f);
        d1s[(4 * g + 3) * 273 + sp] = fmaxf(a.w, 0.f);
    }
    __syncthreads();
    if (t < 112) {
        int par = t / 28, rem2 = t % 28;
        int q = rem2 >> 1, rh = rem2 & 1, r0c = rh * 7;
        int ay = par >> 1, ax = par & 1;
        float acc[7];
        float bv = db2[0];
        #pragma unroll
        for (int r = 0; r < 7; r++) acc[r] = bv;
        #pragma unroll
        for (int dy = 0; dy < 2; dy++)
        #pragma unroll
        for (int dx = 0; dx < 2; dx++) {
            int ky = 2 * dy + ay, kx = 2 * dx + ax;
            const float* inr = d1s + (q + dy + ay) * 17 + r0c + dx + ax;
            const float* wp = ws + (ky * 4 + kx) * 32;
            #pragma unroll 8
            for (int ci = 0; ci < 32; ci++) {
                float w = wp[ci];
                const float* ip = inr + ci * 273;
                #pragma unroll
                for (int r = 0; r < 7; r++) acc[r] += ip[r] * w;
            }
        }
        int oy = 2 * q + ay;
        float* ob = out_recon + b * 784 + oy * 28 + ax;
        #pragma unroll
        for (int r = 0; r < 7; r++) {
            float v = acc[r];
            ob[2 * (r0c + r)] = 1.f / (1.f + __expf(-v));
        }
    }
}

// ---------------- launch ----------------
extern "C" void kernel_launch(void* const* d_in, const int* in_sizes, int n_in,
                              void* d_out, int out_size) {
    const float* x   = (const float*)d_in[0];
    const float* w1  = (const float*)d_in[1];
    const float* b1  = (const float*)d_in[2];
    const float* w2  = (const float*)d_in[3];
    const float* b2  = (const float*)d_in[4];
    const float* w3  = (const float*)d_in[5];
    const float* b3  = (const float*)d_in[6];
    const float* cb  = (const float*)d_in[7];
    const float* dw0 = (const float*)d_in[8];
    const float* db0 = (const float*)d_in[9];
    const float* dw1 = (const float*)d_in[10];
    const float* db1 = (const float*)d_in[11];
    const float* dw2 = (const float*)d_in[12];
    const float* db2 = (const float*)d_in[13];

    float* out = (float*)d_out;
    float* out_recon = out;                       // 3,211,264
    float* out_z     = out_recon + 3211264;       // 12,845,056
    float* out_zq    = out_z + 12845056;          // 12,845,056
    float* out_vq    = out_zq + 12845056;         // 1
    float* out_idx   = out_vq + 1;                // 200,704

    cudaFuncSetAttribute(k_conv2, cudaFuncAttributeMaxDynamicSharedMemorySize, C2_SMEM_WORDS * 4);
    cudaFuncSetAttribute(k_vq,    cudaFuncAttributeMaxDynamicSharedMemorySize, K3_SMEM_WORDS * 4);

    k_prep<<<129, 256>>>(cb, dw0, db0);
    k_prep2<<<1024, 256>>>(dw1);
    k_conv1<<<4096, 256>>>(x, w1, b1);
    k_conv2<<<2048, 224, C2_SMEM_WORDS * 4>>>(w2, b2);
    k_vq<<<1568, 256, K3_SMEM_WORDS * 4>>>(w3, b3, cb, out_z, out_zq, out_idx);
    k_vqred<<<1, 256>>>(out_vq);
    k_dec<<<4096, 256>>>(db1, dw2, db2, out_recon);
}